// round 4
// baseline (speedup 1.0000x reference)
#include <cuda_runtime.h>

// BatchDelayProcessor: lag-D feedback delay line.
//   c_k = x_k + FB * c_{k-1}         (carry per chain, c_{-1} = 0)
//   out_k = (1-MIX) * x_k + MIX * c_{k-1}
// Each (b, j) with j in [0, D) is an independent length-NBLK chain.
//
// R3: sm_103 ptxas requires 256-bit width for L2::evict_* on BOTH ld and st,
// and 256-bit alignment is impossible here (block stride 22050 floats, mod-8=2).
// So: plain ld.global.nc front-batched (MLP=20) + st.global.cs streaming
// stores (keeps the write stream from displacing the input in L2 across
// graph replays).

#define D_SAMP   22050
#define T_LEN    441000
#define B_SZ     64
#define NBLK     20          // T_LEN / D_SAMP
#define FB       0.3f
#define MIXC     0.5f

#define HD       (D_SAMP / 2)                 // 11025 float2 chains per batch row
#define NCHAINS  ((long long)B_SZ * HD)       // 705600

__device__ __forceinline__ float2 ld_x(const void* p) {
    float2 v;
    asm volatile("ld.global.nc.v2.f32 {%0,%1}, [%2];"
                 : "=f"(v.x), "=f"(v.y) : "l"(p));
    return v;
}

__device__ __forceinline__ void st_o(void* p, float2 v) {
    asm volatile("st.global.cs.v2.f32 [%0], {%1,%2};"
                 :: "l"(p), "f"(v.x), "f"(v.y) : "memory");
}

__global__ __launch_bounds__(256) void delay_kernel(const float* __restrict__ x,
                                                    float* __restrict__ out) {
    long long idx = (long long)blockIdx.x * blockDim.x + threadIdx.x;
    if (idx >= NCHAINS) return;

    int b = (int)(idx / HD);
    int j = (int)(idx % HD) * 2;

    const char* xbase = (const char*)(x + (size_t)b * T_LEN + j);
    char*       obase = (char*)(out + (size_t)b * T_LEN + j);

    const size_t blk_stride = (size_t)D_SAMP * sizeof(float);  // 88200 B

    // Front-batch all loads: independent addresses -> MLP = 20
    float2 xv[NBLK];
#pragma unroll
    for (int k = 0; k < NBLK; k++) {
        xv[k] = ld_x(xbase + (size_t)k * blk_stride);
    }

    float2 c;
    c.x = 0.0f;
    c.y = 0.0f;

#pragma unroll
    for (int k = 0; k < NBLK; k++) {
        float2 o;
        o.x = fmaf(c.x, MIXC, xv[k].x * (1.0f - MIXC));
        o.y = fmaf(c.y, MIXC, xv[k].y * (1.0f - MIXC));
        st_o(obase + (size_t)k * blk_stride, o);
        c.x = fmaf(c.x, FB, xv[k].x);
        c.y = fmaf(c.y, FB, xv[k].y);
    }
}

extern "C" void kernel_launch(void* const* d_in, const int* in_sizes, int n_in,
                              void* d_out, int out_size) {
    const float* x = (const float*)d_in[0];
    float* out = (float*)d_out;

    const int threads = 256;
    const long long nthreads = NCHAINS;
    const int blocks = (int)((nthreads + threads - 1) / threads);
    delay_kernel<<<blocks, threads>>>(x, out);
}

// round 5
// speedup vs baseline: 1.0008x; 1.0008x over previous
#include <cuda_runtime.h>
#include <cstdint>

// BatchDelayProcessor: lag-D feedback delay line.
//   c_k = x_k + FB * c_{k-1}         (carry per chain, c_{-1} = 0)
//   out_k = (1-MIX) * x_k + MIX * c_{k-1}
//
// R4: input fits in L2 (113MB vs 126MB) and graph replays reuse it.
// Static .L2::evict_last is width-restricted on sm_103, but the
// createpolicy + .L2::cache_hint form is not. Mark input loads
// evict_last (protected class -> the 113MB output write stream can't
// displace x), stores stay .cs streaming.

#define D_SAMP   22050
#define T_LEN    441000
#define B_SZ     64
#define NBLK     20          // T_LEN / D_SAMP
#define FB       0.3f
#define MIXC     0.5f

#define HD       (D_SAMP / 2)                 // 11025 float2 chains per batch row
#define NCHAINS  ((long long)B_SZ * HD)       // 705600

__device__ __forceinline__ float2 ld_x(const void* p, uint64_t pol) {
    float2 v;
    asm volatile("ld.global.nc.L2::cache_hint.v2.f32 {%0,%1}, [%2], %3;"
                 : "=f"(v.x), "=f"(v.y) : "l"(p), "l"(pol));
    return v;
}

__device__ __forceinline__ void st_o(void* p, float2 v) {
    asm volatile("st.global.cs.v2.f32 [%0], {%1,%2};"
                 :: "l"(p), "f"(v.x), "f"(v.y) : "memory");
}

__global__ __launch_bounds__(256) void delay_kernel(const float* __restrict__ x,
                                                    float* __restrict__ out) {
    long long idx = (long long)blockIdx.x * blockDim.x + threadIdx.x;
    if (idx >= NCHAINS) return;

    // evict_last policy: keep input lines in the protected L2 class
    uint64_t pol;
    asm("createpolicy.fractional.L2::evict_last.b64 %0, 1.0;" : "=l"(pol));

    int b = (int)(idx / HD);
    int j = (int)(idx % HD) * 2;

    const char* xbase = (const char*)(x + (size_t)b * T_LEN + j);
    char*       obase = (char*)(out + (size_t)b * T_LEN + j);

    const size_t blk_stride = (size_t)D_SAMP * sizeof(float);  // 88200 B

    float2 xv[NBLK];
#pragma unroll
    for (int k = 0; k < NBLK; k++) {
        xv[k] = ld_x(xbase + (size_t)k * blk_stride, pol);
    }

    float2 c;
    c.x = 0.0f;
    c.y = 0.0f;

#pragma unroll
    for (int k = 0; k < NBLK; k++) {
        float2 o;
        o.x = fmaf(c.x, MIXC, xv[k].x * (1.0f - MIXC));
        o.y = fmaf(c.y, MIXC, xv[k].y * (1.0f - MIXC));
        st_o(obase + (size_t)k * blk_stride, o);
        c.x = fmaf(c.x, FB, xv[k].x);
        c.y = fmaf(c.y, FB, xv[k].y);
    }
}

extern "C" void kernel_launch(void* const* d_in, const int* in_sizes, int n_in,
                              void* d_out, int out_size) {
    const float* x = (const float*)d_in[0];
    float* out = (float*)d_out;

    const int threads = 256;
    const long long nthreads = NCHAINS;
    const int blocks = (int)((nthreads + threads - 1) / threads);
    delay_kernel<<<blocks, threads>>>(x, out);
}